// round 9
// baseline (speedup 1.0000x reference)
#include <cuda_runtime.h>
#include <cuda_fp16.h>
#include <cstdint>

// ---------------- problem constants ----------------
constexpr int BATCH = 8192;
constexpr int DH    = 1024;

// ---------------- tiling ----------------
constexpr int BM      = 128;   // batch rows per CTA
constexpr int BNG     = 32;    // cols per gate per CTA
constexpr int NTOT    = 128;   // 4 gates x 32
constexpr int BK      = 64;    // K halfs per chunk (128B rows)
constexpr int KITERS  = 32;    // 2048 / 64
constexpr int THREADS = 256;   // 8 warps: 4(M) x 2(N)

constexpr int A_STAGE_BYTES = BM   * 128;                 // 16384
constexpr int B_STAGE_BYTES = NTOT * 128;                 // 16384
constexpr int STAGE_BYTES   = A_STAGE_BYTES + B_STAGE_BYTES;   // 32768
constexpr int MBAR_OFF      = 3 * STAGE_BYTES;                 // 98304
constexpr int SMEM_BYTES    = MBAR_OFF + 64;                   // 98368 -> 2 CTAs/SM

// ---------------- scratch: pre-tiled + pre-swizzled fp16 ----------------
// A: [bt(64)][chunk(32)][128 rows x 128B, XOR-swizzled]  (chunks 0-15: x, 16-31: h)
// B: [jt(32)][chunk(32)][128 rows (g*32+jl) x 128B, XOR-swizzled]
__device__ __align__(128) __half g_sA[64u * 32u * 8192u];   // 32 MB
__device__ __align__(128) __half g_sB[32u * 32u * 8192u];   // 16 MB

template <int N> struct IC { static constexpr int value = N; };

struct Params {
    const float* x;
    const float* h;
    const float* c;
    const float* W[4];
    const float* U[4];
    const float* bias[4];
    float* outh;
    float* outc;
};

// ---------------- helpers ----------------
__device__ __forceinline__ uint32_t smem_u32(const void* p) {
    uint32_t a;
    asm("{ .reg .u64 t; cvta.to.shared.u64 t, %1; cvt.u32.u64 %0, t; }" : "=r"(a) : "l"(p));
    return a;
}
__device__ __forceinline__ void mbar_init(uint32_t a, uint32_t cnt) {
    asm volatile("mbarrier.init.shared.b64 [%0], %1;" :: "r"(a), "r"(cnt) : "memory");
}
__device__ __forceinline__ void mbar_arrive(uint32_t a) {
    asm volatile("mbarrier.arrive.shared.b64 _, [%0];" :: "r"(a) : "memory");
}
__device__ __forceinline__ void mbar_expect_tx(uint32_t a, uint32_t tx) {
    asm volatile("mbarrier.arrive.expect_tx.shared.b64 _, [%0], %1;" :: "r"(a), "r"(tx) : "memory");
}
__device__ __forceinline__ void mbar_wait(uint32_t a, uint32_t parity) {
    asm volatile(
        "{\n\t.reg .pred P;\n"
        "W%=:\n\t"
        "mbarrier.try_wait.parity.shared::cta.b64 P, [%0], %1, 0x989680;\n\t"
        "@!P bra W%=;\n\t}"
        :: "r"(a), "r"(parity) : "memory");
}
__device__ __forceinline__ void bulk_g2s(uint32_t dst, const void* src, uint32_t bytes, uint32_t mbar) {
    asm volatile(
        "cp.async.bulk.shared::cluster.global.mbarrier::complete_tx::bytes [%0], [%1], %2, [%3];"
        :: "r"(dst), "l"(src), "r"(bytes), "r"(mbar) : "memory");
}
__device__ __forceinline__ void ldsm_x4(uint32_t* r, uint32_t addr) {
    asm volatile("ldmatrix.sync.aligned.m8n8.x4.shared.b16 {%0,%1,%2,%3}, [%4];"
        : "=r"(r[0]), "=r"(r[1]), "=r"(r[2]), "=r"(r[3]) : "r"(addr));
}
__device__ __forceinline__ void mma_f16(float* d, const uint32_t* a, const uint32_t* b) {
    asm volatile(
        "mma.sync.aligned.m16n8k16.row.col.f32.f16.f16.f32 "
        "{%0,%1,%2,%3}, {%4,%5,%6,%7}, {%8,%9}, {%0,%1,%2,%3};"
        : "+f"(d[0]), "+f"(d[1]), "+f"(d[2]), "+f"(d[3])
        : "r"(a[0]), "r"(a[1]), "r"(a[2]), "r"(a[3]), "r"(b[0]), "r"(b[1]));
}
__device__ __forceinline__ float sigm(float v) {
    return __fdividef(1.0f, 1.0f + __expf(-v));
}
__device__ __forceinline__ float ftanh(float v) {
    return __fmaf_rn(2.0f, sigm(2.0f * v), -1.0f);
}

// ---------------- pass 1: fp32 -> tiled/swizzled fp16 ----------------
constexpr int ACH = 64 * 32 * 128 * 8;   // 2097152 16B-dst-chunks
constexpr int BCH = 32 * 32 * 128 * 8;   // 1048576
constexpr int TOTAL_CH = ACH + BCH;      // 3145728

__global__ void __launch_bounds__(256) convert_kernel(Params p)
{
    const int idx = blockIdx.x * 256 + threadIdx.x;
    if (idx >= TOTAL_CH) return;

    const float* src;
    __half* dst;
    if (idx < ACH) {
        const int c16 = idx & 7;
        const int r   = (idx >> 3) & 127;
        const int kc  = (idx >> 10) & 31;
        const int bt  = idx >> 15;
        src = (kc < 16 ? p.x : p.h)
              + (size_t)(bt * 128 + r) * 1024 + (kc & 15) * 64 + c16 * 8;
        dst = g_sA + ((size_t)(bt * 32 + kc) * 128 + r) * 64 + ((c16 ^ (r & 7)) * 8);
    } else {
        const int t   = idx - ACH;
        const int c16 = t & 7;
        const int r   = (t >> 3) & 127;        // g*32 + jl
        const int kc  = (t >> 10) & 31;
        const int jt  = t >> 15;
        const int g   = r >> 5, jl = r & 31;
        src = (kc < 16 ? p.W[g] : p.U[g])
              + (size_t)(jt * 32 + jl) * 1024 + (kc & 15) * 64 + c16 * 8;
        dst = g_sB + ((size_t)(jt * 32 + kc) * 128 + r) * 64 + ((c16 ^ (r & 7)) * 8);
    }
    const float4 v0 = *(const float4*)(src);
    const float4 v1 = *(const float4*)(src + 4);
    __half2 h0 = __floats2half2_rn(v0.x, v0.y);
    __half2 h1 = __floats2half2_rn(v0.z, v0.w);
    __half2 h2 = __floats2half2_rn(v1.x, v1.y);
    __half2 h3 = __floats2half2_rn(v1.z, v1.w);
    uint4 pk;
    pk.x = *(const uint32_t*)&h0;
    pk.y = *(const uint32_t*)&h1;
    pk.z = *(const uint32_t*)&h2;
    pk.w = *(const uint32_t*)&h3;
    *(uint4*)dst = pk;
}

// ---------------- pass 2: fp16 GEMM + fused LSTM epilogue ----------------
__global__ void __launch_bounds__(THREADS, 2)
lstm_mma_f16_kernel(Params p)
{
    extern __shared__ __align__(128) char smem[];
    const uint32_t sbase = smem_u32(smem);

    const int tid  = threadIdx.x;
    const int wid  = tid >> 5;
    const int lane = tid & 31;
    const int wm   = wid >> 1;        // 0..3 : rows wm*32
    const int wn   = wid & 1;         // 0..1 : j cols wn*16 per gate
    const int g4   = lane >> 2;
    const int t4   = lane & 3;

    const int bm = blockIdx.y * BM;
    const int j0 = blockIdx.x * BNG;

    const __half* tileA = g_sA + (size_t)blockIdx.y * (32u * 8192u);
    const __half* tileB = g_sB + (size_t)blockIdx.x * (32u * 8192u);

    const uint32_t mb = sbase + MBAR_OFF;
    auto FULL = [&](int s) { return mb + (uint32_t)s * 8u; };
    auto FREE = [&](int s) { return mb + 24u + (uint32_t)s * 8u; };

    if (tid == 0) {
        #pragma unroll
        for (int s = 0; s < 3; s++) { mbar_init(FULL(s), 1); mbar_init(FREE(s), 8); }
    }
    __syncthreads();

    // ---- prologue: stage chunks 0,1,2 ----
    if (tid == 0) {
        #pragma unroll
        for (int s = 0; s < 3; s++) {
            mbar_expect_tx(FULL(s), STAGE_BYTES);
            bulk_g2s(sbase + s * STAGE_BYTES,                 tileA + s * 8192, A_STAGE_BYTES, FULL(s));
            bulk_g2s(sbase + s * STAGE_BYTES + A_STAGE_BYTES, tileB + s * 8192, B_STAGE_BYTES, FULL(s));
        }
    }

    // ---- accumulators ----
    float acc[2][4][2][4];
    #pragma unroll
    for (int a = 0; a < 2; a++)
        #pragma unroll
        for (int b = 0; b < 4; b++)
            #pragma unroll
            for (int s = 0; s < 2; s++)
                #pragma unroll
                for (int q = 0; q < 4; q++) acc[a][b][s][q] = 0.0f;

    // ---- per-lane ldmatrix row/col selection ----
    const int a_rsel = (lane & 7) + (((lane >> 3) & 1) << 3);
    const int a_ckad = (lane >> 4);
    const int b_rsel = (lane & 7) + ((lane >> 4) << 3);
    const int b_ckad = ((lane >> 3) & 1);

    uint32_t a_base[2]; int a_rx[2];
    #pragma unroll
    for (int mt = 0; mt < 2; mt++) {
        const int row = wm * 32 + mt * 16 + a_rsel;
        a_base[mt] = sbase + (uint32_t)(row * 128);
        a_rx[mt]   = row & 7;
    }
    uint32_t b_base[4]; int b_rx[4];
    #pragma unroll
    for (int g = 0; g < 4; g++) {
        const int row = g * 32 + wn * 16 + b_rsel;
        b_base[g] = sbase + (uint32_t)(A_STAGE_BYTES + row * 128);
        b_rx[g]   = row & 7;
    }

    // one pipeline step: chunk kt lives in buffer S; use index = kt/3.
    // Producer role rotates across warps (kt&7); FREE arrive fires right after
    // the last ldsm of the buffer (the trailing mma chain reads registers only).
    auto body = [&](auto Sc, int kt, int use, bool do_stage) {
        constexpr int S = decltype(Sc)::value;
        constexpr uint32_t soff = (uint32_t)S * STAGE_BYTES;
        const uint32_t parity = (uint32_t)(use & 1);

        mbar_wait(FULL(S), parity);

        #pragma unroll
        for (int kk = 0; kk < 4; kk++) {
            uint32_t afr[2][4];
            #pragma unroll
            for (int mt = 0; mt < 2; mt++) {
                const int ck = kk * 2 + a_ckad;
                ldsm_x4(afr[mt], a_base[mt] + soff + ((ck ^ a_rx[mt]) << 4));
            }
            uint32_t bfr[4][4];
            #pragma unroll
            for (int g = 0; g < 4; g++) {
                const int ck = kk * 2 + b_ckad;
                ldsm_x4(bfr[g], b_base[g] + soff + ((ck ^ b_rx[g]) << 4));
            }
            if (kk == 3 && lane == 0) mbar_arrive(FREE(S));   // regs hold all data
            #pragma unroll
            for (int mt = 0; mt < 2; mt++)
                #pragma unroll
                for (int g = 0; g < 4; g++) {
                    mma_f16(acc[mt][g][0], afr[mt], &bfr[g][0]);
                    mma_f16(acc[mt][g][1], afr[mt], &bfr[g][2]);
                }
        }

        if (do_stage && wid == (kt & 7) && lane == 0) {
            const int kn = kt + 3;
            // wait until ALL warps finished reading buffer S this use
            mbar_wait(FREE(S), parity);
            mbar_expect_tx(FULL(S), STAGE_BYTES);
            bulk_g2s(sbase + soff,                 tileA + kn * 8192, A_STAGE_BYTES, FULL(S));
            bulk_g2s(sbase + soff + A_STAGE_BYTES, tileB + kn * 8192, B_STAGE_BYTES, FULL(S));
        }
    };

    // ---- main loop: 32 chunks = 10 x 3 + 2 (staging stops at chunk 31) ----
    for (int use = 0; use < 9; use++) {
        body(IC<0>{}, use * 3 + 0, use, true);
        body(IC<1>{}, use * 3 + 1, use, true);
        body(IC<2>{}, use * 3 + 2, use, true);
    }
    body(IC<0>{}, 27, 9, true);
    body(IC<1>{}, 28, 9, true);
    body(IC<2>{}, 29, 9, false);
    body(IC<0>{}, 30, 10, false);
    body(IC<1>{}, 31, 10, false);

    // ---- fused epilogue (register-resident) ----
    {
        float2 bb[4][2];
        #pragma unroll
        for (int g = 0; g < 4; g++)
            #pragma unroll
            for (int s2 = 0; s2 < 2; s2++)
                bb[g][s2] = *(const float2*)(p.bias[g] + j0 + wn * 16 + s2 * 8 + 2 * t4);

        #pragma unroll
        for (int mt = 0; mt < 2; mt++) {
            #pragma unroll
            for (int hh = 0; hh < 2; hh++) {
                const int row = bm + wm * 32 + mt * 16 + g4 + hh * 8;
                const size_t ro = (size_t)row * 1024 + j0 + wn * 16;
                #pragma unroll
                for (int s2 = 0; s2 < 2; s2++) {
                    const int co = s2 * 8 + 2 * t4;
                    const float2 cv = *(const float2*)(p.c + ro + co);
                    const int q = hh * 2;

                    const float i0 = sigm(acc[mt][0][s2][q]     + bb[0][s2].x);
                    const float i1 = sigm(acc[mt][0][s2][q + 1] + bb[0][s2].y);
                    const float f0 = sigm(acc[mt][1][s2][q]     + bb[1][s2].x);
                    const float f1 = sigm(acc[mt][1][s2][q + 1] + bb[1][s2].y);
                    const float o0 = sigm(acc[mt][2][s2][q]     + bb[2][s2].x);
                    const float o1 = sigm(acc[mt][2][s2][q + 1] + bb[2][s2].y);
                    const float c0 = ftanh(acc[mt][3][s2][q]     + bb[3][s2].x);
                    const float c1 = ftanh(acc[mt][3][s2][q + 1] + bb[3][s2].y);

                    const float nc0 = f0 * cv.x + i0 * c0;
                    const float nc1 = f1 * cv.y + i1 * c1;
                    float2 oh, oc;
                    oc.x = nc0; oc.y = nc1;
                    oh.x = o0 * ftanh(nc0);
                    oh.y = o1 * ftanh(nc1);
                    *(float2*)(p.outh + ro + co) = oh;
                    *(float2*)(p.outc + ro + co) = oc;
                }
            }
        }
    }
}

// ---------------- launch ----------------
extern "C" void kernel_launch(void* const* d_in, const int* in_sizes, int n_in,
                              void* d_out, int out_size)
{
    (void)in_sizes; (void)n_in; (void)out_size;

    Params p;
    p.x = (const float*)d_in[0];
    p.h = (const float*)d_in[1];
    p.c = (const float*)d_in[2];
    for (int g = 0; g < 4; g++) {   // (Wi,bi,Ui),(Wf,bf,Uf),(Wo,bo,Uo),(Wc,bc,Uc)
        p.W[g]    = (const float*)d_in[3 + 3 * g];
        p.bias[g] = (const float*)d_in[4 + 3 * g];
        p.U[g]    = (const float*)d_in[5 + 3 * g];
    }
    float* out = (float*)d_out;
    p.outh = out;
    p.outc = out + (size_t)BATCH * DH;

    static bool configured = false;
    if (!configured) {
        cudaFuncSetAttribute(lstm_mma_f16_kernel,
                             cudaFuncAttributeMaxDynamicSharedMemorySize, SMEM_BYTES);
        configured = true;
    }

    convert_kernel<<<(TOTAL_CH + 255) / 256, 256>>>(p);

    dim3 grid(DH / BNG, BATCH / BM);   // (32, 64)
    lstm_mma_f16_kernel<<<grid, THREADS, SMEM_BYTES>>>(p);
}

// round 10
// speedup vs baseline: 1.5019x; 1.5019x over previous
#include <cuda_runtime.h>
#include <cuda_fp16.h>
#include <cstdint>

// ---------------- problem constants ----------------
constexpr int BATCH = 8192;
constexpr int DH    = 1024;

// ---------------- tiling ----------------
constexpr int BM      = 128;   // batch rows per CTA
constexpr int BNG     = 32;    // cols per gate per CTA
constexpr int NTOT    = 128;   // 4 gates x 32
constexpr int BK      = 64;    // K halfs per chunk (128B rows)
constexpr int KITERS  = 32;    // 2048 / 64
constexpr int THREADS = 256;   // 8 warps: 4(M) x 2(N)

constexpr int A_STAGE_BYTES = BM   * 128;                 // 16384
constexpr int B_STAGE_BYTES = NTOT * 128;                 // 16384
constexpr int STAGE_BYTES   = A_STAGE_BYTES + B_STAGE_BYTES;   // 32768
constexpr int MBAR_OFF      = 3 * STAGE_BYTES;                 // 98304 (3 FULL barriers)
constexpr int CNT_OFF       = MBAR_OFF + 32;                   // 3 u32 counters
constexpr int SMEM_BYTES    = MBAR_OFF + 64;                   // 98368 -> 2 CTAs/SM

// ---------------- scratch: pre-tiled + pre-swizzled fp16 ----------------
// A: [bt(64)][chunk(32)][128 rows x 128B, XOR-swizzled]  (chunks 0-15: x, 16-31: h)
// B: [jt(32)][chunk(32)][128 rows (g*32+jl) x 128B, XOR-swizzled]
__device__ __align__(128) __half g_sA[64u * 32u * 8192u];   // 32 MB
__device__ __align__(128) __half g_sB[32u * 32u * 8192u];   // 16 MB

template <int N> struct IC { static constexpr int value = N; };

struct Params {
    const float* x;
    const float* h;
    const float* c;
    const float* W[4];
    const float* U[4];
    const float* bias[4];
    float* outh;
    float* outc;
};

// ---------------- helpers ----------------
__device__ __forceinline__ uint32_t smem_u32(const void* p) {
    uint32_t a;
    asm("{ .reg .u64 t; cvta.to.shared.u64 t, %1; cvt.u32.u64 %0, t; }" : "=r"(a) : "l"(p));
    return a;
}
__device__ __forceinline__ void mbar_init(uint32_t a, uint32_t cnt) {
    asm volatile("mbarrier.init.shared.b64 [%0], %1;" :: "r"(a), "r"(cnt) : "memory");
}
__device__ __forceinline__ void mbar_expect_tx(uint32_t a, uint32_t tx) {
    asm volatile("mbarrier.arrive.expect_tx.shared.b64 _, [%0], %1;" :: "r"(a), "r"(tx) : "memory");
}
__device__ __forceinline__ void mbar_wait(uint32_t a, uint32_t parity) {
    asm volatile(
        "{\n\t.reg .pred P;\n"
        "W%=:\n\t"
        "mbarrier.try_wait.parity.shared::cta.b64 P, [%0], %1, 0x989680;\n\t"
        "@!P bra W%=;\n\t}"
        :: "r"(a), "r"(parity) : "memory");
}
__device__ __forceinline__ void bulk_g2s(uint32_t dst, const void* src, uint32_t bytes, uint32_t mbar) {
    asm volatile(
        "cp.async.bulk.shared::cluster.global.mbarrier::complete_tx::bytes [%0], [%1], %2, [%3];"
        :: "r"(dst), "l"(src), "r"(bytes), "r"(mbar) : "memory");
}
__device__ __forceinline__ void ldsm_x4(uint32_t* r, uint32_t addr) {
    asm volatile("ldmatrix.sync.aligned.m8n8.x4.shared.b16 {%0,%1,%2,%3}, [%4];"
        : "=r"(r[0]), "=r"(r[1]), "=r"(r[2]), "=r"(r[3]) : "r"(addr));
}
__device__ __forceinline__ void mma_f16(float* d, const uint32_t* a, const uint32_t* b) {
    asm volatile(
        "mma.sync.aligned.m16n8k16.row.col.f32.f16.f16.f32 "
        "{%0,%1,%2,%3}, {%4,%5,%6,%7}, {%8,%9}, {%0,%1,%2,%3};"
        : "+f"(d[0]), "+f"(d[1]), "+f"(d[2]), "+f"(d[3])
        : "r"(a[0]), "r"(a[1]), "r"(a[2]), "r"(a[3]), "r"(b[0]), "r"(b[1]));
}
__device__ __forceinline__ float sigm(float v) {
    return __fdividef(1.0f, 1.0f + __expf(-v));
}
__device__ __forceinline__ float ftanh(float v) {
    return __fmaf_rn(2.0f, sigm(2.0f * v), -1.0f);
}

// ---------------- pass 1: fp32 -> tiled/swizzled fp16 ----------------
constexpr int ACH = 64 * 32 * 128 * 8;   // 2097152 16B-dst-chunks
constexpr int BCH = 32 * 32 * 128 * 8;   // 1048576
constexpr int TOTAL_CH = ACH + BCH;      // 3145728

__global__ void __launch_bounds__(256) convert_kernel(Params p)
{
    const int idx = blockIdx.x * 256 + threadIdx.x;
    if (idx >= TOTAL_CH) return;

    const float* src;
    __half* dst;
    if (idx < ACH) {
        const int c16 = idx & 7;
        const int r   = (idx >> 3) & 127;
        const int kc  = (idx >> 10) & 31;
        const int bt  = idx >> 15;
        src = (kc < 16 ? p.x : p.h)
              + (size_t)(bt * 128 + r) * 1024 + (kc & 15) * 64 + c16 * 8;
        dst = g_sA + ((size_t)(bt * 32 + kc) * 128 + r) * 64 + ((c16 ^ (r & 7)) * 8);
    } else {
        const int t   = idx - ACH;
        const int c16 = t & 7;
        const int r   = (t >> 3) & 127;        // g*32 + jl
        const int kc  = (t >> 10) & 31;
        const int jt  = t >> 15;
        const int g   = r >> 5, jl = r & 31;
        src = (kc < 16 ? p.W[g] : p.U[g])
              + (size_t)(jt * 32 + jl) * 1024 + (kc & 15) * 64 + c16 * 8;
        dst = g_sB + ((size_t)(jt * 32 + kc) * 128 + r) * 64 + ((c16 ^ (r & 7)) * 8);
    }
    const float4 v0 = *(const float4*)(src);
    const float4 v1 = *(const float4*)(src + 4);
    __half2 h0 = __floats2half2_rn(v0.x, v0.y);
    __half2 h1 = __floats2half2_rn(v0.z, v0.w);
    __half2 h2 = __floats2half2_rn(v1.x, v1.y);
    __half2 h3 = __floats2half2_rn(v1.z, v1.w);
    uint4 pk;
    pk.x = *(const uint32_t*)&h0;
    pk.y = *(const uint32_t*)&h1;
    pk.z = *(const uint32_t*)&h2;
    pk.w = *(const uint32_t*)&h3;
    *(uint4*)dst = pk;
}

// ---------------- pass 2: fp16 GEMM + fused LSTM epilogue ----------------
__global__ void __launch_bounds__(THREADS, 2)
lstm_mma_f16_kernel(Params p)
{
    extern __shared__ __align__(128) char smem[];
    const uint32_t sbase = smem_u32(smem);

    const int tid  = threadIdx.x;
    const int wid  = tid >> 5;
    const int lane = tid & 31;
    const int wm   = wid >> 1;        // 0..3 : rows wm*32
    const int wn   = wid & 1;         // 0..1 : j cols wn*16 per gate
    const int g4   = lane >> 2;
    const int t4   = lane & 3;

    const int bm = blockIdx.y * BM;
    const int j0 = blockIdx.x * BNG;

    const __half* tileA = g_sA + (size_t)blockIdx.y * (32u * 8192u);
    const __half* tileB = g_sB + (size_t)blockIdx.x * (32u * 8192u);

    const uint32_t mb = sbase + MBAR_OFF;
    auto FULL = [&](int s) { return mb + (uint32_t)s * 8u; };
    uint32_t* cnt = (uint32_t*)(smem + CNT_OFF);

    if (tid == 0) {
        #pragma unroll
        for (int s = 0; s < 3; s++) { mbar_init(FULL(s), 1); cnt[s] = 0; }
    }
    __syncthreads();

    // ---- prologue: stage chunks 0,1,2 ----
    if (tid == 0) {
        #pragma unroll
        for (int s = 0; s < 3; s++) {
            mbar_expect_tx(FULL(s), STAGE_BYTES);
            bulk_g2s(sbase + s * STAGE_BYTES,                 tileA + s * 8192, A_STAGE_BYTES, FULL(s));
            bulk_g2s(sbase + s * STAGE_BYTES + A_STAGE_BYTES, tileB + s * 8192, B_STAGE_BYTES, FULL(s));
        }
    }

    // ---- accumulators ----
    float acc[2][4][2][4];
    #pragma unroll
    for (int a = 0; a < 2; a++)
        #pragma unroll
        for (int b = 0; b < 4; b++)
            #pragma unroll
            for (int s = 0; s < 2; s++)
                #pragma unroll
                for (int q = 0; q < 4; q++) acc[a][b][s][q] = 0.0f;

    // ---- per-lane ldmatrix row/col selection ----
    const int a_rsel = (lane & 7) + (((lane >> 3) & 1) << 3);
    const int a_ckad = (lane >> 4);
    const int b_rsel = (lane & 7) + ((lane >> 4) << 3);
    const int b_ckad = ((lane >> 3) & 1);

    uint32_t a_base[2]; int a_rx[2];
    #pragma unroll
    for (int mt = 0; mt < 2; mt++) {
        const int row = wm * 32 + mt * 16 + a_rsel;
        a_base[mt] = sbase + (uint32_t)(row * 128);
        a_rx[mt]   = row & 7;
    }
    uint32_t b_base[4]; int b_rx[4];
    #pragma unroll
    for (int g = 0; g < 4; g++) {
        const int row = g * 32 + wn * 16 + b_rsel;
        b_base[g] = sbase + (uint32_t)(A_STAGE_BYTES + row * 128);
        b_rx[g]   = row & 7;
    }

    // one pipeline step: chunk kt lives in buffer S; use index = kt/3.
    // End-of-chunk: each warp's lane0 bumps cnt[S] (after its MMAs have issued,
    // so its ldsm reads are physically complete). The warp observing the 8th
    // increment of this use is the LAST reader and immediately stages chunk kt+3
    // — no designated producer, no blocking wait, no convoy.
    auto body = [&](auto Sc, int kt, int use, bool do_stage) {
        constexpr int S = decltype(Sc)::value;
        constexpr uint32_t soff = (uint32_t)S * STAGE_BYTES;
        const uint32_t parity = (uint32_t)(use & 1);

        mbar_wait(FULL(S), parity);

        #pragma unroll
        for (int kk = 0; kk < 4; kk++) {
            uint32_t afr[2][4];
            #pragma unroll
            for (int mt = 0; mt < 2; mt++) {
                const int ck = kk * 2 + a_ckad;
                ldsm_x4(afr[mt], a_base[mt] + soff + ((ck ^ a_rx[mt]) << 4));
            }
            uint32_t bfr[4][4];
            #pragma unroll
            for (int g = 0; g < 4; g++) {
                const int ck = kk * 2 + b_ckad;
                ldsm_x4(bfr[g], b_base[g] + soff + ((ck ^ b_rx[g]) << 4));
            }
            #pragma unroll
            for (int mt = 0; mt < 2; mt++)
                #pragma unroll
                for (int g = 0; g < 4; g++) {
                    mma_f16(acc[mt][g][0], afr[mt], &bfr[g][0]);
                    mma_f16(acc[mt][g][1], afr[mt], &bfr[g][2]);
                }
        }

        if (do_stage && lane == 0) {
            const uint32_t old = atomicAdd(&cnt[S], 1u);
            if ((old & 7u) == 7u) {            // last reader of this use -> stage
                const int kn = kt + 3;
                mbar_expect_tx(FULL(S), STAGE_BYTES);
                bulk_g2s(sbase + soff,                 tileA + kn * 8192, A_STAGE_BYTES, FULL(S));
                bulk_g2s(sbase + soff + A_STAGE_BYTES, tileB + kn * 8192, B_STAGE_BYTES, FULL(S));
            }
        }
    };

    // ---- main loop: 32 chunks = 10 x 3 + 2 (staging stops at chunk 31) ----
    for (int use = 0; use < 9; use++) {
        body(IC<0>{}, use * 3 + 0, use, true);
        body(IC<1>{}, use * 3 + 1, use, true);
        body(IC<2>{}, use * 3 + 2, use, true);
    }
    body(IC<0>{}, 27, 9, true);
    body(IC<1>{}, 28, 9, true);
    body(IC<2>{}, 29, 9, false);
    body(IC<0>{}, 30, 10, false);
    body(IC<1>{}, 31, 10, false);

    // ---- fused epilogue (register-resident) ----
    {
        float2 bb[4][2];
        #pragma unroll
        for (int g = 0; g < 4; g++)
            #pragma unroll
            for (int s2 = 0; s2 < 2; s2++)
                bb[g][s2] = *(const float2*)(p.bias[g] + j0 + wn * 16 + s2 * 8 + 2 * t4);

        #pragma unroll
        for (int mt = 0; mt < 2; mt++) {
            #pragma unroll
            for (int hh = 0; hh < 2; hh++) {
                const int row = bm + wm * 32 + mt * 16 + g4 + hh * 8;
                const size_t ro = (size_t)row * 1024 + j0 + wn * 16;
                #pragma unroll
                for (int s2 = 0; s2 < 2; s2++) {
                    const int co = s2 * 8 + 2 * t4;
                    const float2 cv = *(const float2*)(p.c + ro + co);
                    const int q = hh * 2;

                    const float i0 = sigm(acc[mt][0][s2][q]     + bb[0][s2].x);
                    const float i1 = sigm(acc[mt][0][s2][q + 1] + bb[0][s2].y);
                    const float f0 = sigm(acc[mt][1][s2][q]     + bb[1][s2].x);
                    const float f1 = sigm(acc[mt][1][s2][q + 1] + bb[1][s2].y);
                    const float o0 = sigm(acc[mt][2][s2][q]     + bb[2][s2].x);
                    const float o1 = sigm(acc[mt][2][s2][q + 1] + bb[2][s2].y);
                    const float c0 = ftanh(acc[mt][3][s2][q]     + bb[3][s2].x);
                    const float c1 = ftanh(acc[mt][3][s2][q + 1] + bb[3][s2].y);

                    const float nc0 = f0 * cv.x + i0 * c0;
                    const float nc1 = f1 * cv.y + i1 * c1;
                    float2 oh, oc;
                    oc.x = nc0; oc.y = nc1;
                    oh.x = o0 * ftanh(nc0);
                    oh.y = o1 * ftanh(nc1);
                    *(float2*)(p.outh + ro + co) = oh;
                    *(float2*)(p.outc + ro + co) = oc;
                }
            }
        }
    }
}

// ---------------- launch ----------------
extern "C" void kernel_launch(void* const* d_in, const int* in_sizes, int n_in,
                              void* d_out, int out_size)
{
    (void)in_sizes; (void)n_in; (void)out_size;

    Params p;
    p.x = (const float*)d_in[0];
    p.h = (const float*)d_in[1];
    p.c = (const float*)d_in[2];
    for (int g = 0; g < 4; g++) {   // (Wi,bi,Ui),(Wf,bf,Uf),(Wo,bo,Uo),(Wc,bc,Uc)
        p.W[g]    = (const float*)d_in[3 + 3 * g];
        p.bias[g] = (const float*)d_in[4 + 3 * g];
        p.U[g]    = (const float*)d_in[5 + 3 * g];
    }
    float* out = (float*)d_out;
    p.outh = out;
    p.outc = out + (size_t)BATCH * DH;

    static bool configured = false;
    if (!configured) {
        cudaFuncSetAttribute(lstm_mma_f16_kernel,
                             cudaFuncAttributeMaxDynamicSharedMemorySize, SMEM_BYTES);
        configured = true;
    }

    convert_kernel<<<(TOTAL_CH + 255) / 256, 256>>>(p);

    dim3 grid(DH / BNG, BATCH / BM);   // (32, 64)
    lstm_mma_f16_kernel<<<grid, THREADS, SMEM_BYTES>>>(p);
}

// round 11
// speedup vs baseline: 1.5062x; 1.0029x over previous
#include <cuda_runtime.h>
#include <cuda_fp16.h>
#include <cstdint>

// ---------------- problem constants ----------------
constexpr int BATCH = 8192;
constexpr int DH    = 1024;

// ---------------- tiling ----------------
constexpr int BM      = 128;   // batch rows per CTA
constexpr int BNG     = 32;    // cols per gate per CTA
constexpr int NTOT    = 128;   // 4 gates x 32
constexpr int BK      = 64;    // K halfs per chunk (128B rows)
constexpr int KITERS  = 32;    // 2048 / 64
constexpr int THREADS = 256;   // 8 warps: 4(M) x 2(N)

constexpr int A_STAGE_BYTES = BM   * 128;                 // 16384
constexpr int B_STAGE_BYTES = NTOT * 128;                 // 16384
constexpr int STAGE_BYTES   = A_STAGE_BYTES + B_STAGE_BYTES;   // 32768
constexpr int MBAR_OFF      = 3 * STAGE_BYTES;                 // 98304 (3 FULL barriers)
constexpr int CNT_OFF       = MBAR_OFF + 32;                   // 3 u32 counters
constexpr int SMEM_BYTES    = MBAR_OFF + 64;                   // 98368 -> 2 CTAs/SM

// ---------------- scratch: pre-tiled + pre-swizzled fp16 ----------------
// A: [bt(64)][chunk(32)][128 rows x 128B, XOR-swizzled]  (chunks 0-15: x, 16-31: h)
// B: [jt(32)][chunk(32)][128 rows (g*32+jl) x 128B, XOR-swizzled]
__device__ __align__(128) __half g_sA[64u * 32u * 8192u];   // 32 MB
__device__ __align__(128) __half g_sB[32u * 32u * 8192u];   // 16 MB

template <int N> struct IC { static constexpr int value = N; };

struct Params {
    const float* x;
    const float* h;
    const float* c;
    const float* W[4];
    const float* U[4];
    const float* bias[4];
    float* outh;
    float* outc;
};

// ---------------- helpers ----------------
__device__ __forceinline__ uint32_t smem_u32(const void* p) {
    uint32_t a;
    asm("{ .reg .u64 t; cvta.to.shared.u64 t, %1; cvt.u32.u64 %0, t; }" : "=r"(a) : "l"(p));
    return a;
}
__device__ __forceinline__ void mbar_init(uint32_t a, uint32_t cnt) {
    asm volatile("mbarrier.init.shared.b64 [%0], %1;" :: "r"(a), "r"(cnt) : "memory");
}
__device__ __forceinline__ void mbar_expect_tx(uint32_t a, uint32_t tx) {
    asm volatile("mbarrier.arrive.expect_tx.shared.b64 _, [%0], %1;" :: "r"(a), "r"(tx) : "memory");
}
__device__ __forceinline__ void mbar_wait(uint32_t a, uint32_t parity) {
    asm volatile(
        "{\n\t.reg .pred P;\n"
        "W%=:\n\t"
        "mbarrier.try_wait.parity.shared::cta.b64 P, [%0], %1, 0x989680;\n\t"
        "@!P bra W%=;\n\t}"
        :: "r"(a), "r"(parity) : "memory");
}
__device__ __forceinline__ void bulk_g2s(uint32_t dst, const void* src, uint32_t bytes, uint32_t mbar) {
    asm volatile(
        "cp.async.bulk.shared::cluster.global.mbarrier::complete_tx::bytes [%0], [%1], %2, [%3];"
        :: "r"(dst), "l"(src), "r"(bytes), "r"(mbar) : "memory");
}
__device__ __forceinline__ void prefetch_l2(const void* p) {
    asm volatile("prefetch.global.L2 [%0];" :: "l"(p));
}
__device__ __forceinline__ void ldsm_x4(uint32_t* r, uint32_t addr) {
    asm volatile("ldmatrix.sync.aligned.m8n8.x4.shared.b16 {%0,%1,%2,%3}, [%4];"
        : "=r"(r[0]), "=r"(r[1]), "=r"(r[2]), "=r"(r[3]) : "r"(addr));
}
__device__ __forceinline__ void mma_f16(float* d, const uint32_t* a, const uint32_t* b) {
    asm volatile(
        "mma.sync.aligned.m16n8k16.row.col.f32.f16.f16.f32 "
        "{%0,%1,%2,%3}, {%4,%5,%6,%7}, {%8,%9}, {%0,%1,%2,%3};"
        : "+f"(d[0]), "+f"(d[1]), "+f"(d[2]), "+f"(d[3])
        : "r"(a[0]), "r"(a[1]), "r"(a[2]), "r"(a[3]), "r"(b[0]), "r"(b[1]));
}
__device__ __forceinline__ float sigm(float v) {
    return __fdividef(1.0f, 1.0f + __expf(-v));
}
__device__ __forceinline__ float ftanh(float v) {
    return __fmaf_rn(2.0f, sigm(2.0f * v), -1.0f);
}

// ---------------- pass 1: fp32 -> tiled/swizzled fp16 ----------------
constexpr int ACH = 64 * 32 * 128 * 8;   // 2097152 16B-dst-chunks
constexpr int BCH = 32 * 32 * 128 * 8;   // 1048576
constexpr int TOTAL_CH = ACH + BCH;      // 3145728

__global__ void __launch_bounds__(512) convert_kernel(Params p)
{
    const int idx = blockIdx.x * 512 + threadIdx.x;
    if (idx >= TOTAL_CH) return;

    const float* src;
    __half* dst;
    if (idx < ACH) {
        const int c16 = idx & 7;
        const int r   = (idx >> 3) & 127;
        const int kc  = (idx >> 10) & 31;
        const int bt  = idx >> 15;
        src = (kc < 16 ? p.x : p.h)
              + (size_t)(bt * 128 + r) * 1024 + (kc & 15) * 64 + c16 * 8;
        dst = g_sA + ((size_t)(bt * 32 + kc) * 128 + r) * 64 + ((c16 ^ (r & 7)) * 8);
    } else {
        const int t   = idx - ACH;
        const int c16 = t & 7;
        const int r   = (t >> 3) & 127;        // g*32 + jl
        const int kc  = (t >> 10) & 31;
        const int jt  = t >> 15;
        const int g   = r >> 5, jl = r & 31;
        src = (kc < 16 ? p.W[g] : p.U[g])
              + (size_t)(jt * 32 + jl) * 1024 + (kc & 15) * 64 + c16 * 8;
        dst = g_sB + ((size_t)(jt * 32 + kc) * 128 + r) * 64 + ((c16 ^ (r & 7)) * 8);
    }
    const float4 v0 = *(const float4*)(src);
    const float4 v1 = *(const float4*)(src + 4);
    __half2 h0 = __floats2half2_rn(v0.x, v0.y);
    __half2 h1 = __floats2half2_rn(v0.z, v0.w);
    __half2 h2 = __floats2half2_rn(v1.x, v1.y);
    __half2 h3 = __floats2half2_rn(v1.z, v1.w);
    uint4 pk;
    pk.x = *(const uint32_t*)&h0;
    pk.y = *(const uint32_t*)&h1;
    pk.z = *(const uint32_t*)&h2;
    pk.w = *(const uint32_t*)&h3;
    *(uint4*)dst = pk;
}

// ---------------- pass 2: fp16 GEMM + fused LSTM epilogue ----------------
__global__ void __launch_bounds__(THREADS, 2)
lstm_mma_f16_kernel(Params p)
{
    extern __shared__ __align__(128) char smem[];
    const uint32_t sbase = smem_u32(smem);

    const int tid  = threadIdx.x;
    const int wid  = tid >> 5;
    const int lane = tid & 31;
    const int wm   = wid >> 1;        // 0..3 : rows wm*32
    const int wn   = wid & 1;         // 0..1 : j cols wn*16 per gate
    const int g4   = lane >> 2;
    const int t4   = lane & 3;

    const int bm = blockIdx.y * BM;
    const int j0 = blockIdx.x * BNG;

    const __half* tileA = g_sA + (size_t)blockIdx.y * (32u * 8192u);
    const __half* tileB = g_sB + (size_t)blockIdx.x * (32u * 8192u);

    const uint32_t mb = sbase + MBAR_OFF;
    auto FULL = [&](int s) { return mb + (uint32_t)s * 8u; };
    uint32_t* cnt = (uint32_t*)(smem + CNT_OFF);

    if (tid == 0) {
        #pragma unroll
        for (int s = 0; s < 3; s++) { mbar_init(FULL(s), 1); cnt[s] = 0; }
    }
    __syncthreads();

    // ---- prologue: stage chunks 0,1,2 ----
    if (tid == 0) {
        #pragma unroll
        for (int s = 0; s < 3; s++) {
            mbar_expect_tx(FULL(s), STAGE_BYTES);
            bulk_g2s(sbase + s * STAGE_BYTES,                 tileA + s * 8192, A_STAGE_BYTES, FULL(s));
            bulk_g2s(sbase + s * STAGE_BYTES + A_STAGE_BYTES, tileB + s * 8192, B_STAGE_BYTES, FULL(s));
        }
    }

    // ---- warm L2 for epilogue inputs (c rows + bias) while GEMM runs ----
    {
        #pragma unroll
        for (int mt = 0; mt < 2; mt++)
            #pragma unroll
            for (int hh = 0; hh < 2; hh++) {
                const int row = bm + wm * 32 + mt * 16 + g4 + hh * 8;
                prefetch_l2(p.c + (size_t)row * 1024 + j0 + wn * 16 + 2 * t4);
            }
        if (lane < 4) prefetch_l2(p.bias[lane] + j0);
    }

    // ---- accumulators ----
    float acc[2][4][2][4];
    #pragma unroll
    for (int a = 0; a < 2; a++)
        #pragma unroll
        for (int b = 0; b < 4; b++)
            #pragma unroll
            for (int s = 0; s < 2; s++)
                #pragma unroll
                for (int q = 0; q < 4; q++) acc[a][b][s][q] = 0.0f;

    // ---- per-lane ldmatrix row/col selection ----
    const int a_rsel = (lane & 7) + (((lane >> 3) & 1) << 3);
    const int a_ckad = (lane >> 4);
    const int b_rsel = (lane & 7) + ((lane >> 4) << 3);
    const int b_ckad = ((lane >> 3) & 1);

    uint32_t a_base[2]; int a_rx[2];
    #pragma unroll
    for (int mt = 0; mt < 2; mt++) {
        const int row = wm * 32 + mt * 16 + a_rsel;
        a_base[mt] = sbase + (uint32_t)(row * 128);
        a_rx[mt]   = row & 7;
    }
    uint32_t b_base[4]; int b_rx[4];
    #pragma unroll
    for (int g = 0; g < 4; g++) {
        const int row = g * 32 + wn * 16 + b_rsel;
        b_base[g] = sbase + (uint32_t)(A_STAGE_BYTES + row * 128);
        b_rx[g]   = row & 7;
    }

    // one pipeline step: chunk kt lives in buffer S; use index = kt/3.
    // End-of-chunk: each warp's lane0 bumps cnt[S] (after its MMAs have issued,
    // so its ldsm reads are physically complete). The warp observing the 8th
    // increment of this use is the LAST reader and immediately stages chunk kt+3
    // — no designated producer, no blocking wait, no convoy.
    auto body = [&](auto Sc, int kt, int use, bool do_stage) {
        constexpr int S = decltype(Sc)::value;
        constexpr uint32_t soff = (uint32_t)S * STAGE_BYTES;
        const uint32_t parity = (uint32_t)(use & 1);

        mbar_wait(FULL(S), parity);

        #pragma unroll
        for (int kk = 0; kk < 4; kk++) {
            uint32_t afr[2][4];
            #pragma unroll
            for (int mt = 0; mt < 2; mt++) {
                const int ck = kk * 2 + a_ckad;
                ldsm_x4(afr[mt], a_base[mt] + soff + ((ck ^ a_rx[mt]) << 4));
            }
            uint32_t bfr[4][4];
            #pragma unroll
            for (int g = 0; g < 4; g++) {
                const int ck = kk * 2 + b_ckad;
                ldsm_x4(bfr[g], b_base[g] + soff + ((ck ^ b_rx[g]) << 4));
            }
            #pragma unroll
            for (int mt = 0; mt < 2; mt++)
                #pragma unroll
                for (int g = 0; g < 4; g++) {
                    mma_f16(acc[mt][g][0], afr[mt], &bfr[g][0]);
                    mma_f16(acc[mt][g][1], afr[mt], &bfr[g][2]);
                }
        }

        if (do_stage && lane == 0) {
            const uint32_t old = atomicAdd(&cnt[S], 1u);
            if ((old & 7u) == 7u) {            // last reader of this use -> stage
                const int kn = kt + 3;
                mbar_expect_tx(FULL(S), STAGE_BYTES);
                bulk_g2s(sbase + soff,                 tileA + kn * 8192, A_STAGE_BYTES, FULL(S));
                bulk_g2s(sbase + soff + A_STAGE_BYTES, tileB + kn * 8192, B_STAGE_BYTES, FULL(S));
            }
        }
    };

    // ---- main loop: 32 chunks = 10 x 3 + 2 (staging stops at chunk 31) ----
    for (int use = 0; use < 9; use++) {
        body(IC<0>{}, use * 3 + 0, use, true);
        body(IC<1>{}, use * 3 + 1, use, true);
        body(IC<2>{}, use * 3 + 2, use, true);
    }
    body(IC<0>{}, 27, 9, true);
    body(IC<1>{}, 28, 9, true);
    body(IC<2>{}, 29, 9, false);
    body(IC<0>{}, 30, 10, false);
    body(IC<1>{}, 31, 10, false);

    // ---- fused epilogue (register-resident) ----
    {
        float2 bb[4][2];
        #pragma unroll
        for (int g = 0; g < 4; g++)
            #pragma unroll
            for (int s2 = 0; s2 < 2; s2++)
                bb[g][s2] = *(const float2*)(p.bias[g] + j0 + wn * 16 + s2 * 8 + 2 * t4);

        #pragma unroll
        for (int mt = 0; mt < 2; mt++) {
            #pragma unroll
            for (int hh = 0; hh < 2; hh++) {
                const int row = bm + wm * 32 + mt * 16 + g4 + hh * 8;
                const size_t ro = (size_t)row * 1024 + j0 + wn * 16;
                #pragma unroll
                for (int s2 = 0; s2 < 2; s2++) {
                    const int co = s2 * 8 + 2 * t4;
                    const float2 cv = *(const float2*)(p.c + ro + co);
                    const int q = hh * 2;

                    const float i0 = sigm(acc[mt][0][s2][q]     + bb[0][s2].x);
                    const float i1 = sigm(acc[mt][0][s2][q + 1] + bb[0][s2].y);
                    const float f0 = sigm(acc[mt][1][s2][q]     + bb[1][s2].x);
                    const float f1 = sigm(acc[mt][1][s2][q + 1] + bb[1][s2].y);
                    const float o0 = sigm(acc[mt][2][s2][q]     + bb[2][s2].x);
                    const float o1 = sigm(acc[mt][2][s2][q + 1] + bb[2][s2].y);
                    const float c0 = ftanh(acc[mt][3][s2][q]     + bb[3][s2].x);
                    const float c1 = ftanh(acc[mt][3][s2][q + 1] + bb[3][s2].y);

                    const float nc0 = f0 * cv.x + i0 * c0;
                    const float nc1 = f1 * cv.y + i1 * c1;
                    float2 oh, oc;
                    oc.x = nc0; oc.y = nc1;
                    oh.x = o0 * ftanh(nc0);
                    oh.y = o1 * ftanh(nc1);
                    *(float2*)(p.outh + ro + co) = oh;
                    *(float2*)(p.outc + ro + co) = oc;
                }
            }
        }
    }
}

// ---------------- launch ----------------
extern "C" void kernel_launch(void* const* d_in, const int* in_sizes, int n_in,
                              void* d_out, int out_size)
{
    (void)in_sizes; (void)n_in; (void)out_size;

    Params p;
    p.x = (const float*)d_in[0];
    p.h = (const float*)d_in[1];
    p.c = (const float*)d_in[2];
    for (int g = 0; g < 4; g++) {   // (Wi,bi,Ui),(Wf,bf,Uf),(Wo,bo,Uo),(Wc,bc,Uc)
        p.W[g]    = (const float*)d_in[3 + 3 * g];
        p.bias[g] = (const float*)d_in[4 + 3 * g];
        p.U[g]    = (const float*)d_in[5 + 3 * g];
    }
    float* out = (float*)d_out;
    p.outh = out;
    p.outc = out + (size_t)BATCH * DH;

    static bool configured = false;
    if (!configured) {
        cudaFuncSetAttribute(lstm_mma_f16_kernel,
                             cudaFuncAttributeMaxDynamicSharedMemorySize, SMEM_BYTES);
        configured = true;
    }

    convert_kernel<<<(TOTAL_CH + 511) / 512, 512>>>(p);

    dim3 grid(DH / BNG, BATCH / BM);   // (32, 64)
    lstm_mma_f16_kernel<<<grid, THREADS, SMEM_BYTES>>>(p);
}